// round 3
// baseline (speedup 1.0000x reference)
#include <cuda_runtime.h>

#define N_NODES 50000
#define N_EDGES 800000
#define N_FEATS 64

// Scratch (allocation-free): 4 x 200KB node vecs + 3.2MB packed edges
__device__ float g_deg[N_NODES];
__device__ float g_a[N_NODES];
__device__ float g_b[N_NODES];
__device__ float g_c[N_NODES];
__device__ unsigned g_packed[N_EDGES];   // (row << 16) | col

// ---------------------------------------------------------------------------
// Projection y0 = x[i,:] . w  (warp per node, coalesced 128B rows)
// + deg init (self-loop contributes 1).
// ---------------------------------------------------------------------------
__global__ void k_proj(const float* __restrict__ x,
                       const float* __restrict__ W) {
    int warp = (blockIdx.x * blockDim.x + threadIdx.x) >> 5;
    int lane = threadIdx.x & 31;
    if (warp >= N_NODES) return;
    const float* xr = x + (size_t)warp * N_FEATS;
    float s = xr[lane] * __ldg(W + lane) + xr[lane + 32] * __ldg(W + lane + 32);
    #pragma unroll
    for (int off = 16; off > 0; off >>= 1)
        s += __shfl_xor_sync(0xFFFFFFFFu, s, off);
    if (lane == 0) {
        g_a[warp]   = s;     // y0
        g_deg[warp] = 1.0f;  // self-loop
    }
}

// ---------------------------------------------------------------------------
// Degree at destination, fused with index packing: 4 edges/thread via int4.
// Packs (row<<16)|col into g_packed so edge passes need 0.25 LDG per edge.
// ---------------------------------------------------------------------------
__global__ void __launch_bounds__(128)
k_degpack(const int* __restrict__ row, const int* __restrict__ col) {
    int t = blockIdx.x * blockDim.x + threadIdx.x;
    if (t >= N_EDGES / 4) return;
    int4 r = reinterpret_cast<const int4*>(row)[t];
    int4 c = reinterpret_cast<const int4*>(col)[t];
    uint4 p;
    p.x = ((unsigned)r.x << 16) | (unsigned)c.x;
    p.y = ((unsigned)r.y << 16) | (unsigned)c.y;
    p.z = ((unsigned)r.z << 16) | (unsigned)c.z;
    p.w = ((unsigned)r.w << 16) | (unsigned)c.w;
    reinterpret_cast<uint4*>(g_packed)[t] = p;
    atomicAdd(&g_deg[c.x], 1.0f);
    atomicAdd(&g_deg[c.y], 1.0f);
    atomicAdd(&g_deg[c.z], 1.0f);
    atomicAdd(&g_deg[c.w], 1.0f);
}

// ---------------------------------------------------------------------------
// u0 = rsqrt(deg) * y0 ; duplicate into gather-source and accumulator
// (the accumulator copy IS the self-loop term).
// ---------------------------------------------------------------------------
__global__ void k_scale2() {
    int i = blockIdx.x * blockDim.x + threadIdx.x;
    if (i >= N_NODES) return;
    float v = rsqrtf(g_deg[i]) * g_a[i];
    g_b[i] = v;
    g_c[i] = v;
}

// ---------------------------------------------------------------------------
// Edge pass: dst[col] += src[row]. 4 edges/thread from packed indices:
// one LDG.128 covers 4 edges' worth of (row,col). Gathers batched before
// REDs for MLP=4.
// ---------------------------------------------------------------------------
__global__ void __launch_bounds__(128)
k_edge(const float* __restrict__ src, float* __restrict__ dst) {
    int t = blockIdx.x * blockDim.x + threadIdx.x;
    if (t >= N_EDGES / 4) return;
    uint4 p = reinterpret_cast<const uint4*>(g_packed)[t];
    float v0 = __ldg(src + (p.x >> 16));
    float v1 = __ldg(src + (p.y >> 16));
    float v2 = __ldg(src + (p.z >> 16));
    float v3 = __ldg(src + (p.w >> 16));
    atomicAdd(dst + (p.x & 0xFFFFu), v0);
    atomicAdd(dst + (p.y & 0xFFFFu), v1);
    atomicAdd(dst + (p.z & 0xFFFFu), v2);
    atomicAdd(dst + (p.w & 0xFFFFu), v3);
}

// ---------------------------------------------------------------------------
// Mid-hop: u' = s/deg ; duplicate into next gather-source and accumulator.
// ---------------------------------------------------------------------------
__global__ void k_div2(const float* __restrict__ s,
                       float* __restrict__ u, float* __restrict__ s2) {
    int i = blockIdx.x * blockDim.x + threadIdx.x;
    if (i >= N_NODES) return;
    float v = s[i] / g_deg[i];
    u[i]  = v;
    s2[i] = v;
}

// ---------------------------------------------------------------------------
// Final: out = rsqrt(deg) * s3 + b (in place on d_out).
// ---------------------------------------------------------------------------
__global__ void k_final(float* __restrict__ out, const float* __restrict__ b) {
    int i = blockIdx.x * blockDim.x + threadIdx.x;
    if (i >= N_NODES) return;
    out[i] = rsqrtf(g_deg[i]) * out[i] + __ldg(b);
}

extern "C" void kernel_launch(void* const* d_in, const int* in_sizes, int n_in,
                              void* d_out, int out_size) {
    const float* x  = (const float*)d_in[0];
    const int*   ei = (const int*)d_in[1];   // [2, N_EDGES]
    const float* W  = (const float*)d_in[2]; // [1, N_FEATS]
    const float* b  = (const float*)d_in[3]; // [1]
    float* out = (float*)d_out;              // [N_NODES, 1]

    const int* row = ei;            // gather source
    const int* col = ei + N_EDGES;  // scatter destination

    float* ap; cudaGetSymbolAddress((void**)&ap, g_a);
    float* bp; cudaGetSymbolAddress((void**)&bp, g_b);
    float* cp; cudaGetSymbolAddress((void**)&cp, g_c);

    const int TBn = 256;
    const int TBe = 128;
    int grid_nodes = (N_NODES + TBn - 1) / TBn;
    int grid_proj  = (N_NODES * 32 + TBn - 1) / TBn;
    int grid_edge4 = (N_EDGES / 4 + TBe - 1) / TBe;   // 1563 blocks

    k_proj<<<grid_proj, TBn>>>(x, W);
    k_degpack<<<grid_edge4, TBe>>>(row, col);

    // hop 1: u0 = rsqrt(deg)*y0 -> (g_b src, g_c acc); acc += gather
    k_scale2<<<grid_nodes, TBn>>>();
    k_edge<<<grid_edge4, TBe>>>(bp, cp);

    // hop 2: u1 = s1/deg -> (g_a src, g_b acc)
    k_div2<<<grid_nodes, TBn>>>(cp, ap, bp);
    k_edge<<<grid_edge4, TBe>>>(ap, bp);

    // hop 3: u2 = s2/deg -> (g_c src, out acc)
    k_div2<<<grid_nodes, TBn>>>(bp, cp, out);
    k_edge<<<grid_edge4, TBe>>>(cp, out);

    // out = rsqrt(deg)*s3 + b
    k_final<<<grid_nodes, TBn>>>(out, b);
}